// round 6
// baseline (speedup 1.0000x reference)
#include <cuda_runtime.h>
#include <cuda_fp16.h>

#define N_NODES 50000
#define N_EDGES 1600000
#define NB_SCAN ((N_NODES + 1023) / 1024)  // 49

// ---- scratch (static __device__, no allocs) ----
__device__ int g_degflag[N_NODES + NB_SCAN];  // [0,N): deg, [N,N+NB): lookback flags
__device__ int g_off[N_NODES + 1];
__device__ int g_cur[N_NODES];
__device__ int g_aggr[NB_SCAN];
__device__ unsigned short g_csr[N_EDGES];     // src ids fit in u16 (50000 < 65536)
__device__ __half g_hA[N_NODES * 64];         // layer-1 pre-agg features, fp16
__device__ __half g_hB[N_NODES * 64];         // layer-2 pre-agg features, fp16
__device__ __half g_h3h[N_NODES * 8];         // layer-3 pre-agg, fp16 (7 used + pad)
__device__ float g_wt1[64 * 64];
__device__ float g_wt2[64 * 64];
__device__ float g_wt3[64 * 8];

// ---------------- weight transposes (Wt[k][j] = W[j][k]) ----------------

__global__ void k_prep_w(const float* __restrict__ W1, const float* __restrict__ W2,
                         const float* __restrict__ W3) {
    for (int t = threadIdx.x; t < 64 * 64; t += blockDim.x) {
        int j = t >> 6, k = t & 63;
        g_wt1[k * 64 + j] = W1[t];
        g_wt2[k * 64 + j] = W2[t];
    }
    for (int t = threadIdx.x; t < 64 * 8; t += blockDim.x) {
        int k = t >> 3, j = t & 7;
        g_wt3[t] = (j < 7) ? W3[j * 64 + k] : 0.f;
    }
}

// ---------------- histogram of dst degrees, 8 edges/thread ----------------

__global__ void k_hist(const int* __restrict__ ei) {
    int i = (blockIdx.x * blockDim.x + threadIdx.x) * 8;
    if (i < N_EDGES) {
        int4 dA = *(const int4*)&ei[N_EDGES + i];
        int4 dB = *(const int4*)&ei[N_EDGES + i + 4];
        if ((unsigned)dA.x < N_NODES) atomicAdd(&g_degflag[dA.x], 1);
        if ((unsigned)dA.y < N_NODES) atomicAdd(&g_degflag[dA.y], 1);
        if ((unsigned)dA.z < N_NODES) atomicAdd(&g_degflag[dA.z], 1);
        if ((unsigned)dA.w < N_NODES) atomicAdd(&g_degflag[dA.w], 1);
        if ((unsigned)dB.x < N_NODES) atomicAdd(&g_degflag[dB.x], 1);
        if ((unsigned)dB.y < N_NODES) atomicAdd(&g_degflag[dB.y], 1);
        if ((unsigned)dB.z < N_NODES) atomicAdd(&g_degflag[dB.z], 1);
        if ((unsigned)dB.w < N_NODES) atomicAdd(&g_degflag[dB.w], 1);
    }
}

// ------ single-kernel exclusive scan: 49 co-resident blocks + lookback ------

__global__ __launch_bounds__(1024) void k_scan2() {
    __shared__ int wsum[32];
    __shared__ int s_base;
    int b = blockIdx.x, t = threadIdx.x, lane = t & 31, wid = t >> 5;
    int i = b * 1024 + t;
    int v = (i < N_NODES) ? g_degflag[i] : 0;
    int incl = v;
    #pragma unroll
    for (int o = 1; o < 32; o <<= 1) {
        int x = __shfl_up_sync(~0u, incl, o);
        if (lane >= o) incl += x;
    }
    if (lane == 31) wsum[wid] = incl;
    __syncthreads();
    if (wid == 0) {
        int w = wsum[lane];
        int wi = w;
        #pragma unroll
        for (int o = 1; o < 32; o <<= 1) {
            int x = __shfl_up_sync(~0u, wi, o);
            if (lane >= o) wi += x;
        }
        wsum[lane] = wi - w;  // exclusive warp base
        if (lane == 31) {     // publish block aggregate ASAP
            g_aggr[b] = wi;
            __threadfence();
            atomicExch(&g_degflag[N_NODES + b], 1);
        }
    }
    __syncthreads();
    if (wid == 0) {  // warp-batched lookback over predecessors
        int run = 0;
        for (int base = 0; base < b; base += 32) {
            int j = base + lane;
            int a = 0;
            if (j < b) {
                while (atomicAdd(&g_degflag[N_NODES + j], 0) == 0) {}
                a = atomicAdd(&g_aggr[j], 0);
            }
            #pragma unroll
            for (int o = 16; o > 0; o >>= 1) a += __shfl_down_sync(~0u, a, o);
            run += __shfl_sync(~0u, a, 0);
        }
        if (lane == 0) s_base = run;
    }
    __syncthreads();
    int ex = s_base + wsum[wid] + incl - v;
    if (i < N_NODES) { g_off[i] = ex; g_cur[i] = ex; }
    if (b == NB_SCAN - 1 && t == 0) g_off[N_NODES] = s_base + g_aggr[b];
}

// ---------------- scatter edges into CSC (u16), 8 edges/thread ----------------

__global__ void k_scatter(const int* __restrict__ ei) {
    int i = (blockIdx.x * blockDim.x + threadIdx.x) * 8;
    if (i < N_EDGES) {
        int4 sA = *(const int4*)&ei[i];
        int4 sB = *(const int4*)&ei[i + 4];
        int4 dA = *(const int4*)&ei[N_EDGES + i];
        int4 dB = *(const int4*)&ei[N_EDGES + i + 4];
        int p0 = ((unsigned)dA.x < N_NODES) ? atomicAdd(&g_cur[dA.x], 1) : -1;
        int p1 = ((unsigned)dA.y < N_NODES) ? atomicAdd(&g_cur[dA.y], 1) : -1;
        int p2 = ((unsigned)dA.z < N_NODES) ? atomicAdd(&g_cur[dA.z], 1) : -1;
        int p3 = ((unsigned)dA.w < N_NODES) ? atomicAdd(&g_cur[dA.w], 1) : -1;
        int p4 = ((unsigned)dB.x < N_NODES) ? atomicAdd(&g_cur[dB.x], 1) : -1;
        int p5 = ((unsigned)dB.y < N_NODES) ? atomicAdd(&g_cur[dB.y], 1) : -1;
        int p6 = ((unsigned)dB.z < N_NODES) ? atomicAdd(&g_cur[dB.z], 1) : -1;
        int p7 = ((unsigned)dB.w < N_NODES) ? atomicAdd(&g_cur[dB.w], 1) : -1;
        if (p0 >= 0) g_csr[p0] = (unsigned short)(((unsigned)sA.x < N_NODES) ? sA.x : 0);
        if (p1 >= 0) g_csr[p1] = (unsigned short)(((unsigned)sA.y < N_NODES) ? sA.y : 0);
        if (p2 >= 0) g_csr[p2] = (unsigned short)(((unsigned)sA.z < N_NODES) ? sA.z : 0);
        if (p3 >= 0) g_csr[p3] = (unsigned short)(((unsigned)sA.w < N_NODES) ? sA.w : 0);
        if (p4 >= 0) g_csr[p4] = (unsigned short)(((unsigned)sB.x < N_NODES) ? sB.x : 0);
        if (p5 >= 0) g_csr[p5] = (unsigned short)(((unsigned)sB.y < N_NODES) ? sB.y : 0);
        if (p6 >= 0) g_csr[p6] = (unsigned short)(((unsigned)sB.z < N_NODES) ? sB.z : 0);
        if (p7 >= 0) g_csr[p7] = (unsigned short)(((unsigned)sB.w < N_NODES) ? sB.w : 0);
    }
}

// ---- packed f32x2 helpers (Blackwell FFMA2) ----

__device__ __forceinline__ unsigned long long pack2(float lo, float hi) {
    unsigned long long p;
    asm("mov.b64 %0, {%1, %2};" : "=l"(p) : "f"(lo), "f"(hi));
    return p;
}
__device__ __forceinline__ void unpack2(unsigned long long p, float& lo, float& hi) {
    asm("mov.b64 {%0, %1}, %2;" : "=f"(lo), "=f"(hi) : "l"(p));
}
__device__ __forceinline__ void ffma2(unsigned long long& d, unsigned long long a,
                                      unsigned long long b) {
    asm("fma.rn.f32x2 %0, %1, %2, %0;" : "+l"(d) : "l"(a), "l"(b));
}

// ------- GEMM 64x64 fp32-in -> fp16 out (layer 1) -------

__global__ __launch_bounds__(256) void k_gemm64h(const float* __restrict__ in,
                                                 const float* __restrict__ wt,
                                                 __half* __restrict__ out) {
    __shared__ __align__(16) float sW[64 * 64];
    __shared__ float sX[64 * 65];
    int n0 = blockIdx.x * 64;
    for (int i = threadIdx.x; i < 4096; i += 256) sW[i] = wt[i];
    for (int i = threadIdx.x; i < 4096; i += 256) {
        int n = i >> 6, k = i & 63;
        sX[n * 65 + k] = (n0 + n < N_NODES) ? in[(n0 + n) * 64 + k] : 0.f;
    }
    __syncthreads();
    int tx = threadIdx.x & 15, ty = threadIdx.x >> 4;
    unsigned long long accP[4][2] = {};
    #pragma unroll 8
    for (int k = 0; k < 64; k++) {
        double2 wd = *(const double2*)&sW[k * 64 + tx * 4];
        unsigned long long w01 = __double_as_longlong(wd.x);
        unsigned long long w23 = __double_as_longlong(wd.y);
        #pragma unroll
        for (int i = 0; i < 4; i++) {
            float xv = sX[(ty * 4 + i) * 65 + k];
            unsigned long long xp = pack2(xv, xv);
            ffma2(accP[i][0], xp, w01);
            ffma2(accP[i][1], xp, w23);
        }
    }
    #pragma unroll
    for (int i = 0; i < 4; i++) {
        int n = n0 + ty * 4 + i;
        if (n < N_NODES) {
            float a0, a1, a2, a3;
            unpack2(accP[i][0], a0, a1);
            unpack2(accP[i][1], a2, a3);
            __half2 h0 = __floats2half2_rn(a0, a1);
            __half2 h1 = __floats2half2_rn(a2, a3);
            uint2 pk = {*(unsigned*)&h0, *(unsigned*)&h1};
            *(uint2*)&out[n * 64 + tx * 4] = pk;
        }
    }
}

// ---- shared agg helper: warp gathers+sums one node's 64ch (2 per lane) ----

__device__ __forceinline__ float2 agg_node(const __half2* __restrict__ h2,
                                           int n, int lane) {
    int beg = g_off[n], end = g_off[n + 1];
    float ax = 0.f, ay = 0.f;
    int e = beg;
    for (; e + 4 <= end; e += 4) {
        int s0 = g_csr[e], s1 = g_csr[e + 1], s2 = g_csr[e + 2], s3 = g_csr[e + 3];
        float2 v0 = __half22float2(h2[s0 * 32 + lane]);
        float2 v1 = __half22float2(h2[s1 * 32 + lane]);
        float2 v2 = __half22float2(h2[s2 * 32 + lane]);
        float2 v3 = __half22float2(h2[s3 * 32 + lane]);
        ax += (v0.x + v1.x) + (v2.x + v3.x);
        ay += (v0.y + v1.y) + (v2.y + v3.y);
    }
    for (; e < end; e++) {
        float2 v = __half22float2(h2[g_csr[e] * 32 + lane]);
        ax += v.x; ay += v.y;
    }
    return make_float2(ax, ay);
}

// ---- FUSED: agg(fp16 in) + bias + relu -> smem -> GEMM 64x64 -> fp16 out ----
// 64 dst nodes per block, 256 threads. in != out (agg gathers graph-wide).

__global__ __launch_bounds__(256) void k_agg_gemm64(const __half2* __restrict__ h2,
                                                    const float* __restrict__ bias,
                                                    const float* __restrict__ wt,
                                                    __half* __restrict__ out) {
    __shared__ __align__(16) float sW[64 * 64];
    __shared__ float sX[64 * 66];
    int n0 = blockIdx.x * 64;
    int lane = threadIdx.x & 31, wid = threadIdx.x >> 5;
    for (int i = threadIdx.x; i < 4096; i += 256) sW[i] = wt[i];
    float2 b = ((const float2*)bias)[lane];
    #pragma unroll
    for (int r = 0; r < 8; r++) {
        int nl = wid * 8 + r;
        int n = n0 + nl;
        float rx = 0.f, ry = 0.f;
        if (n < N_NODES) {
            float2 a = agg_node(h2, n, lane);
            rx = fmaxf(a.x + b.x, 0.f);
            ry = fmaxf(a.y + b.y, 0.f);
        }
        sX[nl * 66 + 2 * lane] = rx;
        sX[nl * 66 + 2 * lane + 1] = ry;
    }
    __syncthreads();
    int tx = threadIdx.x & 15, ty = threadIdx.x >> 4;
    unsigned long long accP[4][2] = {};
    #pragma unroll 8
    for (int k = 0; k < 64; k++) {
        double2 wd = *(const double2*)&sW[k * 64 + tx * 4];
        unsigned long long w01 = __double_as_longlong(wd.x);
        unsigned long long w23 = __double_as_longlong(wd.y);
        #pragma unroll
        for (int i = 0; i < 4; i++) {
            float xv = sX[(ty * 4 + i) * 66 + k];
            unsigned long long xp = pack2(xv, xv);
            ffma2(accP[i][0], xp, w01);
            ffma2(accP[i][1], xp, w23);
        }
    }
    #pragma unroll
    for (int i = 0; i < 4; i++) {
        int n = n0 + ty * 4 + i;
        if (n < N_NODES) {
            float a0, a1, a2, a3;
            unpack2(accP[i][0], a0, a1);
            unpack2(accP[i][1], a2, a3);
            __half2 h0 = __floats2half2_rn(a0, a1);
            __half2 h1 = __floats2half2_rn(a2, a3);
            uint2 pk = {*(unsigned*)&h0, *(unsigned*)&h1};
            *(uint2*)&out[n * 64 + tx * 4] = pk;
        }
    }
}

// ---- FUSED: agg(fp16 in) + bias + relu -> smem -> GEMM 64x7 -> fp16 g_h3h ----
// 64 dst nodes per block, 256 threads; gemm phase: 4 threads/node, 2 ch each.

__global__ __launch_bounds__(256) void k_agg_gemm7(const __half2* __restrict__ h2,
                                                   const float* __restrict__ bias) {
    __shared__ float sX[64 * 66];
    __shared__ float sW3[64 * 8];
    int n0 = blockIdx.x * 64;
    int lane = threadIdx.x & 31, wid = threadIdx.x >> 5;
    for (int i = threadIdx.x; i < 512; i += 256) sW3[i] = g_wt3[i];
    float2 b = ((const float2*)bias)[lane];
    #pragma unroll
    for (int r = 0; r < 8; r++) {
        int nl = wid * 8 + r;
        int n = n0 + nl;
        float rx = 0.f, ry = 0.f;
        if (n < N_NODES) {
            float2 a = agg_node(h2, n, lane);
            rx = fmaxf(a.x + b.x, 0.f);
            ry = fmaxf(a.y + b.y, 0.f);
        }
        sX[nl * 66 + 2 * lane] = rx;
        sX[nl * 66 + 2 * lane + 1] = ry;
    }
    __syncthreads();
    int nl = threadIdx.x >> 2, jg = threadIdx.x & 3;  // node-local, channel pair
    int n = n0 + nl;
    float a0 = 0.f, a1 = 0.f;
    #pragma unroll 8
    for (int k = 0; k < 64; k++) {
        float xv = sX[nl * 66 + k];
        a0 += xv * sW3[k * 8 + jg * 2];
        a1 += xv * sW3[k * 8 + jg * 2 + 1];
    }
    if (n < N_NODES) {
        __half2 h = __floats2half2_rn(a0, a1);
        *(__half2*)&g_h3h[n * 8 + jg * 2] = h;
    }
}

// -------- aggregation 7ch (fp16 in) + bias + log_softmax, thread per node --------

__global__ __launch_bounds__(256) void k_agg7(const float* __restrict__ b3,
                                              float* __restrict__ out) {
    int n = blockIdx.x * blockDim.x + threadIdx.x;
    if (n >= N_NODES) return;
    int beg = g_off[n], end = g_off[n + 1];
    const uint4* __restrict__ p = (const uint4*)g_h3h;
    float a[7] = {};
    for (int e = beg; e < end; e++) {
        uint4 q = p[g_csr[e]];
        float2 f0 = __half22float2(*(__half2*)&q.x);
        float2 f1 = __half22float2(*(__half2*)&q.y);
        float2 f2 = __half22float2(*(__half2*)&q.z);
        float2 f3 = __half22float2(*(__half2*)&q.w);
        a[0] += f0.x; a[1] += f0.y; a[2] += f1.x; a[3] += f1.y;
        a[4] += f2.x; a[5] += f2.y; a[6] += f3.x;
    }
    #pragma unroll
    for (int j = 0; j < 7; j++) a[j] += b3[j];
    float m = a[0];
    #pragma unroll
    for (int j = 1; j < 7; j++) m = fmaxf(m, a[j]);
    float se = 0.f;
    #pragma unroll
    for (int j = 0; j < 7; j++) se += __expf(a[j] - m);
    float ls = __logf(se);
    #pragma unroll
    for (int j = 0; j < 7; j++) out[n * 7 + j] = a[j] - m - ls;
}

// ---------------- launch (fork/join: CSC chain overlaps gemm1) ----------------

static cudaStream_t g_s2 = nullptr;
static cudaEvent_t g_evF = nullptr, g_evJ = nullptr;

extern "C" void kernel_launch(void* const* d_in, const int* in_sizes, int n_in,
                              void* d_out, int out_size) {
    const float* x = (const float*)d_in[0];
    const int* ei = (const int*)d_in[1];
    const float* W1 = (const float*)d_in[2];
    const float* b1 = (const float*)d_in[3];
    const float* W2 = (const float*)d_in[4];
    const float* b2 = (const float*)d_in[5];
    const float* W3 = (const float*)d_in[6];
    const float* b3 = (const float*)d_in[7];
    float* out = (float*)d_out;

    if (!g_s2) {
        cudaStreamCreateWithFlags(&g_s2, cudaStreamNonBlocking);
        cudaEventCreateWithFlags(&g_evF, cudaEventDisableTiming);
        cudaEventCreateWithFlags(&g_evJ, cudaEventDisableTiming);
    }

    void *pA, *pB, *pw1, *pw2, *pdf;
    cudaGetSymbolAddress(&pA, g_hA);
    cudaGetSymbolAddress(&pB, g_hB);
    cudaGetSymbolAddress(&pw1, g_wt1);
    cudaGetSymbolAddress(&pw2, g_wt2);
    cudaGetSymbolAddress(&pdf, g_degflag);

    // fork: CSC build on side stream
    cudaEventRecord(g_evF, 0);
    cudaStreamWaitEvent(g_s2, g_evF, 0);
    cudaMemsetAsync(pdf, 0, (N_NODES + NB_SCAN) * sizeof(int), g_s2);
    k_hist<<<(N_EDGES / 8 + 255) / 256, 256, 0, g_s2>>>(ei);
    k_scan2<<<NB_SCAN, 1024, 0, g_s2>>>();
    k_scatter<<<(N_EDGES / 8 + 255) / 256, 256, 0, g_s2>>>(ei);
    cudaEventRecord(g_evJ, g_s2);

    // main stream: weight prep + layer-1 GEMM (independent of CSC)
    k_prep_w<<<1, 256>>>(W1, W2, W3);
    k_gemm64h<<<(N_NODES + 63) / 64, 256>>>(x, (const float*)pw1, (__half*)pA);

    // join
    cudaStreamWaitEvent(0, g_evJ, 0);

    // fused layers
    k_agg_gemm64<<<(N_NODES + 63) / 64, 256>>>((const __half2*)pA, b1,
                                               (const float*)pw2, (__half*)pB);
    k_agg_gemm7<<<(N_NODES + 63) / 64, 256>>>((const __half2*)pB, b2);
    k_agg7<<<(N_NODES + 255) / 256, 256>>>(b3, out);
}

// round 7
// speedup vs baseline: 1.0916x; 1.0916x over previous
#include <cuda_runtime.h>
#include <cuda_fp16.h>

#define N_NODES 50000
#define N_EDGES 1600000
#define NB_SCAN ((N_NODES + 1023) / 1024)  // 49

// ---- scratch (static __device__, no allocs) ----
__device__ int g_degflag[N_NODES + NB_SCAN];  // [0,N): deg, [N,N+NB): lookback flags
__device__ int g_off[N_NODES + 1];
__device__ int g_cur[N_NODES];
__device__ int g_aggr[NB_SCAN];
__device__ unsigned short g_csr[N_EDGES];     // src ids fit in u16 (50000 < 65536)
__device__ __half g_hA[N_NODES * 64];         // pre-agg features, fp16
__device__ float g_bufB[N_NODES * 64];        // post-agg features, fp32
__device__ __half g_h3h[N_NODES * 8];         // layer-3 pre-agg, fp16 (7 used + pad)
__device__ float g_wt1[64 * 64];
__device__ float g_wt2[64 * 64];
__device__ float g_wt3[64 * 8];

// -------- weight transposes (Wt[k][j] = W[j][k]), grid-parallel --------

__global__ void k_prep_w(const float* __restrict__ W1, const float* __restrict__ W2,
                         const float* __restrict__ W3) {
    int t = blockIdx.x * blockDim.x + threadIdx.x;
    if (t < 64 * 64) {
        int j = t >> 6, k = t & 63;
        g_wt1[k * 64 + j] = W1[t];
        g_wt2[k * 64 + j] = W2[t];
    }
    if (t < 64 * 8) {
        int k = t >> 3, j = t & 7;
        g_wt3[t] = (j < 7) ? W3[j * 64 + k] : 0.f;
    }
}

// ---------------- histogram of dst degrees, 8 edges/thread ----------------

__global__ void k_hist(const int* __restrict__ ei) {
    int i = (blockIdx.x * blockDim.x + threadIdx.x) * 8;
    if (i < N_EDGES) {
        int4 dA = *(const int4*)&ei[N_EDGES + i];
        int4 dB = *(const int4*)&ei[N_EDGES + i + 4];
        if ((unsigned)dA.x < N_NODES) atomicAdd(&g_degflag[dA.x], 1);
        if ((unsigned)dA.y < N_NODES) atomicAdd(&g_degflag[dA.y], 1);
        if ((unsigned)dA.z < N_NODES) atomicAdd(&g_degflag[dA.z], 1);
        if ((unsigned)dA.w < N_NODES) atomicAdd(&g_degflag[dA.w], 1);
        if ((unsigned)dB.x < N_NODES) atomicAdd(&g_degflag[dB.x], 1);
        if ((unsigned)dB.y < N_NODES) atomicAdd(&g_degflag[dB.y], 1);
        if ((unsigned)dB.z < N_NODES) atomicAdd(&g_degflag[dB.z], 1);
        if ((unsigned)dB.w < N_NODES) atomicAdd(&g_degflag[dB.w], 1);
    }
}

// ------ single-kernel exclusive scan: 49 co-resident blocks + lookback ------

__global__ __launch_bounds__(1024) void k_scan2() {
    __shared__ int wsum[32];
    __shared__ int s_base;
    int b = blockIdx.x, t = threadIdx.x, lane = t & 31, wid = t >> 5;
    int i = b * 1024 + t;
    int v = (i < N_NODES) ? g_degflag[i] : 0;
    int incl = v;
    #pragma unroll
    for (int o = 1; o < 32; o <<= 1) {
        int x = __shfl_up_sync(~0u, incl, o);
        if (lane >= o) incl += x;
    }
    if (lane == 31) wsum[wid] = incl;
    __syncthreads();
    if (wid == 0) {
        int w = wsum[lane];
        int wi = w;
        #pragma unroll
        for (int o = 1; o < 32; o <<= 1) {
            int x = __shfl_up_sync(~0u, wi, o);
            if (lane >= o) wi += x;
        }
        wsum[lane] = wi - w;  // exclusive warp base
        if (lane == 31) {     // publish block aggregate ASAP
            g_aggr[b] = wi;
            __threadfence();
            atomicExch(&g_degflag[N_NODES + b], 1);
        }
    }
    __syncthreads();
    if (wid == 0) {  // warp-batched lookback over predecessors
        int run = 0;
        for (int base = 0; base < b; base += 32) {
            int j = base + lane;
            int a = 0;
            if (j < b) {
                while (atomicAdd(&g_degflag[N_NODES + j], 0) == 0) {}
                a = atomicAdd(&g_aggr[j], 0);
            }
            #pragma unroll
            for (int o = 16; o > 0; o >>= 1) a += __shfl_down_sync(~0u, a, o);
            run += __shfl_sync(~0u, a, 0);
        }
        if (lane == 0) s_base = run;
    }
    __syncthreads();
    int ex = s_base + wsum[wid] + incl - v;
    if (i < N_NODES) { g_off[i] = ex; g_cur[i] = ex; }
    if (b == NB_SCAN - 1 && t == 0) g_off[N_NODES] = s_base + g_aggr[b];
}

// ---------------- scatter edges into CSC (u16), 8 edges/thread ----------------

__global__ void k_scatter(const int* __restrict__ ei) {
    int i = (blockIdx.x * blockDim.x + threadIdx.x) * 8;
    if (i < N_EDGES) {
        int4 sA = *(const int4*)&ei[i];
        int4 sB = *(const int4*)&ei[i + 4];
        int4 dA = *(const int4*)&ei[N_EDGES + i];
        int4 dB = *(const int4*)&ei[N_EDGES + i + 4];
        int p0 = ((unsigned)dA.x < N_NODES) ? atomicAdd(&g_cur[dA.x], 1) : -1;
        int p1 = ((unsigned)dA.y < N_NODES) ? atomicAdd(&g_cur[dA.y], 1) : -1;
        int p2 = ((unsigned)dA.z < N_NODES) ? atomicAdd(&g_cur[dA.z], 1) : -1;
        int p3 = ((unsigned)dA.w < N_NODES) ? atomicAdd(&g_cur[dA.w], 1) : -1;
        int p4 = ((unsigned)dB.x < N_NODES) ? atomicAdd(&g_cur[dB.x], 1) : -1;
        int p5 = ((unsigned)dB.y < N_NODES) ? atomicAdd(&g_cur[dB.y], 1) : -1;
        int p6 = ((unsigned)dB.z < N_NODES) ? atomicAdd(&g_cur[dB.z], 1) : -1;
        int p7 = ((unsigned)dB.w < N_NODES) ? atomicAdd(&g_cur[dB.w], 1) : -1;
        if (p0 >= 0) g_csr[p0] = (unsigned short)(((unsigned)sA.x < N_NODES) ? sA.x : 0);
        if (p1 >= 0) g_csr[p1] = (unsigned short)(((unsigned)sA.y < N_NODES) ? sA.y : 0);
        if (p2 >= 0) g_csr[p2] = (unsigned short)(((unsigned)sA.z < N_NODES) ? sA.z : 0);
        if (p3 >= 0) g_csr[p3] = (unsigned short)(((unsigned)sA.w < N_NODES) ? sA.w : 0);
        if (p4 >= 0) g_csr[p4] = (unsigned short)(((unsigned)sB.x < N_NODES) ? sB.x : 0);
        if (p5 >= 0) g_csr[p5] = (unsigned short)(((unsigned)sB.y < N_NODES) ? sB.y : 0);
        if (p6 >= 0) g_csr[p6] = (unsigned short)(((unsigned)sB.z < N_NODES) ? sB.z : 0);
        if (p7 >= 0) g_csr[p7] = (unsigned short)(((unsigned)sB.w < N_NODES) ? sB.w : 0);
    }
}

// ---- packed f32x2 helpers (Blackwell FFMA2) ----

__device__ __forceinline__ unsigned long long pack2(float lo, float hi) {
    unsigned long long p;
    asm("mov.b64 %0, {%1, %2};" : "=l"(p) : "f"(lo), "f"(hi));
    return p;
}
__device__ __forceinline__ void unpack2(unsigned long long p, float& lo, float& hi) {
    asm("mov.b64 {%0, %1}, %2;" : "=f"(lo), "=f"(hi) : "l"(p));
}
__device__ __forceinline__ void ffma2(unsigned long long& d, unsigned long long a,
                                      unsigned long long b) {
    asm("fma.rn.f32x2 %0, %1, %2, %0;" : "+l"(d) : "l"(a), "l"(b));
}

// ------- GEMM 64x64 fp32-in -> fp16 out, f32x2 packed FMA -------

__global__ __launch_bounds__(256) void k_gemm64h(const float* __restrict__ in,
                                                 const float* __restrict__ wt,
                                                 __half* __restrict__ out) {
    __shared__ __align__(16) float sW[64 * 64];
    __shared__ float sX[64 * 65];
    int n0 = blockIdx.x * 64;
    for (int i = threadIdx.x; i < 4096; i += 256) sW[i] = wt[i];
    for (int i = threadIdx.x; i < 4096; i += 256) {
        int n = i >> 6, k = i & 63;
        sX[n * 65 + k] = (n0 + n < N_NODES) ? in[(n0 + n) * 64 + k] : 0.f;
    }
    __syncthreads();
    int tx = threadIdx.x & 15, ty = threadIdx.x >> 4;
    unsigned long long accP[4][2] = {};
    #pragma unroll 8
    for (int k = 0; k < 64; k++) {
        double2 wd = *(const double2*)&sW[k * 64 + tx * 4];
        unsigned long long w01 = __double_as_longlong(wd.x);
        unsigned long long w23 = __double_as_longlong(wd.y);
        #pragma unroll
        for (int i = 0; i < 4; i++) {
            float xv = sX[(ty * 4 + i) * 65 + k];
            unsigned long long xp = pack2(xv, xv);
            ffma2(accP[i][0], xp, w01);
            ffma2(accP[i][1], xp, w23);
        }
    }
    #pragma unroll
    for (int i = 0; i < 4; i++) {
        int n = n0 + ty * 4 + i;
        if (n < N_NODES) {
            float a0, a1, a2, a3;
            unpack2(accP[i][0], a0, a1);
            unpack2(accP[i][1], a2, a3);
            __half2 h0 = __floats2half2_rn(a0, a1);
            __half2 h1 = __floats2half2_rn(a2, a3);
            uint2 pk = {*(unsigned*)&h0, *(unsigned*)&h1};
            *(uint2*)&out[n * 64 + tx * 4] = pk;
        }
    }
}

// ---- aggregation 64ch from fp16: warp per dst node, fp32 accum, no atomics ----

template <bool RELU>
__global__ __launch_bounds__(256) void k_agg64h(const __half2* __restrict__ h2,
                                                const float* __restrict__ bias,
                                                float* __restrict__ out) {
    int n = (blockIdx.x * blockDim.x + threadIdx.x) >> 5;
    int lane = threadIdx.x & 31;
    if (n >= N_NODES) return;
    int beg = g_off[n], end = g_off[n + 1];
    float ax = 0.f, ay = 0.f;
    int e = beg;
    for (; e + 4 <= end; e += 4) {
        int s0 = g_csr[e], s1 = g_csr[e + 1], s2 = g_csr[e + 2], s3 = g_csr[e + 3];
        float2 v0 = __half22float2(h2[s0 * 32 + lane]);
        float2 v1 = __half22float2(h2[s1 * 32 + lane]);
        float2 v2 = __half22float2(h2[s2 * 32 + lane]);
        float2 v3 = __half22float2(h2[s3 * 32 + lane]);
        ax += (v0.x + v1.x) + (v2.x + v3.x);
        ay += (v0.y + v1.y) + (v2.y + v3.y);
    }
    for (; e < end; e++) {
        float2 v = __half22float2(h2[g_csr[e] * 32 + lane]);
        ax += v.x; ay += v.y;
    }
    float2 b = ((const float2*)bias)[lane];
    float rx = ax + b.x, ry = ay + b.y;
    if (RELU) { rx = fmaxf(rx, 0.f); ry = fmaxf(ry, 0.f); }
    ((float2*)out)[n * 32 + lane] = make_float2(rx, ry);
}

// -------- layer 3 projection: 64 -> 7 (padded to 8), fp16 out --------

__global__ __launch_bounds__(128) void k_gemm7(const float* __restrict__ in) {
    __shared__ float sX[128 * 65];
    __shared__ float sW[64 * 8];
    int n0 = blockIdx.x * 128;
    for (int i = threadIdx.x; i < 512; i += 128) sW[i] = g_wt3[i];
    for (int i = threadIdx.x; i < 8192; i += 128) {
        int n = i >> 6, k = i & 63;
        sX[n * 65 + k] = (n0 + n < N_NODES) ? in[(n0 + n) * 64 + k] : 0.f;
    }
    __syncthreads();
    int n = n0 + threadIdx.x;
    float a[8] = {};
    #pragma unroll 8
    for (int k = 0; k < 64; k++) {
        float xv = sX[threadIdx.x * 65 + k];
        #pragma unroll
        for (int j = 0; j < 7; j++) a[j] += xv * sW[k * 8 + j];
    }
    if (n < N_NODES) {
        __half2 h0 = __floats2half2_rn(a[0], a[1]);
        __half2 h1 = __floats2half2_rn(a[2], a[3]);
        __half2 h2 = __floats2half2_rn(a[4], a[5]);
        __half2 h3 = __floats2half2_rn(a[6], 0.f);
        uint4 pk = {*(unsigned*)&h0, *(unsigned*)&h1, *(unsigned*)&h2, *(unsigned*)&h3};
        *(uint4*)&g_h3h[n * 8] = pk;
    }
}

// -------- aggregation 7ch (fp16 in) + bias + log_softmax, thread per node --------

__global__ __launch_bounds__(256) void k_agg7(const float* __restrict__ b3,
                                              float* __restrict__ out) {
    int n = blockIdx.x * blockDim.x + threadIdx.x;
    if (n >= N_NODES) return;
    int beg = g_off[n], end = g_off[n + 1];
    const uint4* __restrict__ p = (const uint4*)g_h3h;
    float a[7] = {};
    for (int e = beg; e < end; e++) {
        uint4 q = p[g_csr[e]];
        float2 f0 = __half22float2(*(__half2*)&q.x);
        float2 f1 = __half22float2(*(__half2*)&q.y);
        float2 f2 = __half22float2(*(__half2*)&q.z);
        float2 f3 = __half22float2(*(__half2*)&q.w);
        a[0] += f0.x; a[1] += f0.y; a[2] += f1.x; a[3] += f1.y;
        a[4] += f2.x; a[5] += f2.y; a[6] += f3.x;
    }
    #pragma unroll
    for (int j = 0; j < 7; j++) a[j] += b3[j];
    float m = a[0];
    #pragma unroll
    for (int j = 1; j < 7; j++) m = fmaxf(m, a[j]);
    float se = 0.f;
    #pragma unroll
    for (int j = 0; j < 7; j++) se += __expf(a[j] - m);
    float ls = __logf(se);
    #pragma unroll
    for (int j = 0; j < 7; j++) out[n * 7 + j] = a[j] - m - ls;
}

// ---------------- launch (fork/join: CSC chain overlaps gemm1) ----------------

static cudaStream_t g_s2 = nullptr;
static cudaEvent_t g_evF = nullptr, g_evJ = nullptr;

extern "C" void kernel_launch(void* const* d_in, const int* in_sizes, int n_in,
                              void* d_out, int out_size) {
    const float* x = (const float*)d_in[0];
    const int* ei = (const int*)d_in[1];
    const float* W1 = (const float*)d_in[2];
    const float* b1 = (const float*)d_in[3];
    const float* W2 = (const float*)d_in[4];
    const float* b2 = (const float*)d_in[5];
    const float* W3 = (const float*)d_in[6];
    const float* b3 = (const float*)d_in[7];
    float* out = (float*)d_out;

    if (!g_s2) {
        cudaStreamCreateWithFlags(&g_s2, cudaStreamNonBlocking);
        cudaEventCreateWithFlags(&g_evF, cudaEventDisableTiming);
        cudaEventCreateWithFlags(&g_evJ, cudaEventDisableTiming);
    }

    void *pA, *pB, *pw1, *pw2, *pdf;
    cudaGetSymbolAddress(&pA, g_hA);
    cudaGetSymbolAddress(&pB, g_bufB);
    cudaGetSymbolAddress(&pw1, g_wt1);
    cudaGetSymbolAddress(&pw2, g_wt2);
    cudaGetSymbolAddress(&pdf, g_degflag);

    // fork: CSC build on side stream
    cudaEventRecord(g_evF, 0);
    cudaStreamWaitEvent(g_s2, g_evF, 0);
    cudaMemsetAsync(pdf, 0, (N_NODES + NB_SCAN) * sizeof(int), g_s2);
    k_hist<<<(N_EDGES / 8 + 255) / 256, 256, 0, g_s2>>>(ei);
    k_scan2<<<NB_SCAN, 1024, 0, g_s2>>>();
    k_scatter<<<(N_EDGES / 8 + 255) / 256, 256, 0, g_s2>>>(ei);
    cudaEventRecord(g_evJ, g_s2);

    // main stream: weight prep + layer-1 GEMM (independent of CSC)
    k_prep_w<<<16, 256>>>(W1, W2, W3);
    k_gemm64h<<<(N_NODES + 63) / 64, 256>>>(x, (const float*)pw1, (__half*)pA);

    // join
    cudaStreamWaitEvent(0, g_evJ, 0);

    // layer 2
    k_agg64h<true><<<(N_NODES * 32 + 255) / 256, 256>>>((const __half2*)pA, b1, (float*)pB);
    k_gemm64h<<<(N_NODES + 63) / 64, 256>>>((const float*)pB, (const float*)pw2, (__half*)pA);
    // layer 3
    k_agg64h<true><<<(N_NODES * 32 + 255) / 256, 256>>>((const __half2*)pA, b2, (float*)pB);
    k_gemm7<<<(N_NODES + 127) / 128, 128>>>((const float*)pB);
    k_agg7<<<(N_NODES + 255) / 256, 256>>>(b3, out);
}

// round 8
// speedup vs baseline: 1.2143x; 1.1123x over previous
#include <cuda_runtime.h>
#include <cuda_fp16.h>

#define N_NODES 50000
#define N_EDGES 1600000
#define BKT 128  // fixed bucket capacity per dst (deg ~ Poisson(32); P(>128) ~ 1e-40)

// ---- scratch (static __device__, no allocs) ----
__device__ int g_cnt[N_NODES];                         // per-dst degree counters
__device__ __align__(16) unsigned short g_bucket[N_NODES * BKT];  // src ids per dst
__device__ __half g_hA[N_NODES * 64];    // pre-agg features, fp16
__device__ float g_bufB[N_NODES * 64];   // post-agg features, fp32
__device__ __half g_h3h[N_NODES * 8];    // layer-3 pre-agg, fp16 (7 used + pad)
__device__ float g_wt1[64 * 64];
__device__ float g_wt2[64 * 64];
__device__ float g_wt3[64 * 8];

// -------- weight transposes (Wt[k][j] = W[j][k]), grid-parallel --------

__global__ void k_prep_w(const float* __restrict__ W1, const float* __restrict__ W2,
                         const float* __restrict__ W3) {
    int t = blockIdx.x * blockDim.x + threadIdx.x;
    if (t < 64 * 64) {
        int j = t >> 6, k = t & 63;
        g_wt1[k * 64 + j] = W1[t];
        g_wt2[k * 64 + j] = W2[t];
    }
    if (t < 64 * 8) {
        int k = t >> 3, j = t & 7;
        g_wt3[t] = (j < 7) ? W3[j * 64 + k] : 0.f;
    }
}

// ------ direct bucket scatter: no hist, no scan; 8 edges/thread ------

__global__ void k_scatter(const int* __restrict__ ei) {
    int i = (blockIdx.x * blockDim.x + threadIdx.x) * 8;
    if (i < N_EDGES) {
        int4 sA = *(const int4*)&ei[i];
        int4 sB = *(const int4*)&ei[i + 4];
        int4 dA = *(const int4*)&ei[N_EDGES + i];
        int4 dB = *(const int4*)&ei[N_EDGES + i + 4];
        int p0 = ((unsigned)dA.x < N_NODES) ? atomicAdd(&g_cnt[dA.x], 1) : -1;
        int p1 = ((unsigned)dA.y < N_NODES) ? atomicAdd(&g_cnt[dA.y], 1) : -1;
        int p2 = ((unsigned)dA.z < N_NODES) ? atomicAdd(&g_cnt[dA.z], 1) : -1;
        int p3 = ((unsigned)dA.w < N_NODES) ? atomicAdd(&g_cnt[dA.w], 1) : -1;
        int p4 = ((unsigned)dB.x < N_NODES) ? atomicAdd(&g_cnt[dB.x], 1) : -1;
        int p5 = ((unsigned)dB.y < N_NODES) ? atomicAdd(&g_cnt[dB.y], 1) : -1;
        int p6 = ((unsigned)dB.z < N_NODES) ? atomicAdd(&g_cnt[dB.z], 1) : -1;
        int p7 = ((unsigned)dB.w < N_NODES) ? atomicAdd(&g_cnt[dB.w], 1) : -1;
        if ((unsigned)p0 < BKT) g_bucket[dA.x * BKT + p0] = (unsigned short)sA.x;
        if ((unsigned)p1 < BKT) g_bucket[dA.y * BKT + p1] = (unsigned short)sA.y;
        if ((unsigned)p2 < BKT) g_bucket[dA.z * BKT + p2] = (unsigned short)sA.z;
        if ((unsigned)p3 < BKT) g_bucket[dA.w * BKT + p3] = (unsigned short)sA.w;
        if ((unsigned)p4 < BKT) g_bucket[dB.x * BKT + p4] = (unsigned short)sB.x;
        if ((unsigned)p5 < BKT) g_bucket[dB.y * BKT + p5] = (unsigned short)sB.y;
        if ((unsigned)p6 < BKT) g_bucket[dB.z * BKT + p6] = (unsigned short)sB.z;
        if ((unsigned)p7 < BKT) g_bucket[dB.w * BKT + p7] = (unsigned short)sB.w;
    }
}

// ---- packed f32x2 helpers (Blackwell FFMA2) ----

__device__ __forceinline__ unsigned long long pack2(float lo, float hi) {
    unsigned long long p;
    asm("mov.b64 %0, {%1, %2};" : "=l"(p) : "f"(lo), "f"(hi));
    return p;
}
__device__ __forceinline__ void unpack2(unsigned long long p, float& lo, float& hi) {
    asm("mov.b64 {%0, %1}, %2;" : "=f"(lo), "=f"(hi) : "l"(p));
}
__device__ __forceinline__ void ffma2(unsigned long long& d, unsigned long long a,
                                      unsigned long long b) {
    asm("fma.rn.f32x2 %0, %1, %2, %0;" : "+l"(d) : "l"(a), "l"(b));
}

// ------- GEMM 64x64 fp32-in -> fp16 out, f32x2 packed FMA -------

__global__ __launch_bounds__(256) void k_gemm64h(const float* __restrict__ in,
                                                 const float* __restrict__ wt,
                                                 __half* __restrict__ out) {
    __shared__ __align__(16) float sW[64 * 64];
    __shared__ float sX[64 * 65];
    int n0 = blockIdx.x * 64;
    for (int i = threadIdx.x; i < 4096; i += 256) sW[i] = wt[i];
    for (int i = threadIdx.x; i < 4096; i += 256) {
        int n = i >> 6, k = i & 63;
        sX[n * 65 + k] = (n0 + n < N_NODES) ? in[(n0 + n) * 64 + k] : 0.f;
    }
    __syncthreads();
    int tx = threadIdx.x & 15, ty = threadIdx.x >> 4;
    unsigned long long accP[4][2] = {};
    #pragma unroll 8
    for (int k = 0; k < 64; k++) {
        double2 wd = *(const double2*)&sW[k * 64 + tx * 4];
        unsigned long long w01 = __double_as_longlong(wd.x);
        unsigned long long w23 = __double_as_longlong(wd.y);
        #pragma unroll
        for (int i = 0; i < 4; i++) {
            float xv = sX[(ty * 4 + i) * 65 + k];
            unsigned long long xp = pack2(xv, xv);
            ffma2(accP[i][0], xp, w01);
            ffma2(accP[i][1], xp, w23);
        }
    }
    #pragma unroll
    for (int i = 0; i < 4; i++) {
        int n = n0 + ty * 4 + i;
        if (n < N_NODES) {
            float a0, a1, a2, a3;
            unpack2(accP[i][0], a0, a1);
            unpack2(accP[i][1], a2, a3);
            __half2 h0 = __floats2half2_rn(a0, a1);
            __half2 h1 = __floats2half2_rn(a2, a3);
            uint2 pk = {*(unsigned*)&h0, *(unsigned*)&h1};
            *(uint2*)&out[n * 64 + tx * 4] = pk;
        }
    }
}

// ---- aggregation 64ch from fp16: warp per dst node, 8 gathers in flight ----

template <bool RELU>
__global__ __launch_bounds__(256) void k_agg64h(const __half2* __restrict__ h2,
                                                const float* __restrict__ bias,
                                                float* __restrict__ out) {
    int n = (blockIdx.x * blockDim.x + threadIdx.x) >> 5;
    int lane = threadIdx.x & 31;
    if (n >= N_NODES) return;
    int cnt = min(g_cnt[n], BKT);
    const uint4* __restrict__ idx4 = (const uint4*)(g_bucket + n * BKT);  // 8 u16/load
    float ax = 0.f, ay = 0.f;
    int e = 0;
    for (; e + 8 <= cnt; e += 8) {
        uint4 q = idx4[e >> 3];
        int s0 = q.x & 0xFFFF, s1 = q.x >> 16;
        int s2 = q.y & 0xFFFF, s3 = q.y >> 16;
        int s4 = q.z & 0xFFFF, s5 = q.z >> 16;
        int s6 = q.w & 0xFFFF, s7 = q.w >> 16;
        float2 v0 = __half22float2(h2[s0 * 32 + lane]);
        float2 v1 = __half22float2(h2[s1 * 32 + lane]);
        float2 v2 = __half22float2(h2[s2 * 32 + lane]);
        float2 v3 = __half22float2(h2[s3 * 32 + lane]);
        float2 v4 = __half22float2(h2[s4 * 32 + lane]);
        float2 v5 = __half22float2(h2[s5 * 32 + lane]);
        float2 v6 = __half22float2(h2[s6 * 32 + lane]);
        float2 v7 = __half22float2(h2[s7 * 32 + lane]);
        ax += ((v0.x + v1.x) + (v2.x + v3.x)) + ((v4.x + v5.x) + (v6.x + v7.x));
        ay += ((v0.y + v1.y) + (v2.y + v3.y)) + ((v4.y + v5.y) + (v6.y + v7.y));
    }
    for (; e < cnt; e++) {
        float2 v = __half22float2(h2[g_bucket[n * BKT + e] * 32 + lane]);
        ax += v.x; ay += v.y;
    }
    float2 b = ((const float2*)bias)[lane];
    float rx = ax + b.x, ry = ay + b.y;
    if (RELU) { rx = fmaxf(rx, 0.f); ry = fmaxf(ry, 0.f); }
    ((float2*)out)[n * 32 + lane] = make_float2(rx, ry);
}

// -------- layer 3 projection: 64 -> 7 (padded to 8), fp16 out --------

__global__ __launch_bounds__(128) void k_gemm7(const float* __restrict__ in) {
    __shared__ float sX[128 * 65];
    __shared__ float sW[64 * 8];
    int n0 = blockIdx.x * 128;
    for (int i = threadIdx.x; i < 512; i += 128) sW[i] = g_wt3[i];
    for (int i = threadIdx.x; i < 8192; i += 128) {
        int n = i >> 6, k = i & 63;
        sX[n * 65 + k] = (n0 + n < N_NODES) ? in[(n0 + n) * 64 + k] : 0.f;
    }
    __syncthreads();
    int n = n0 + threadIdx.x;
    float a[8] = {};
    #pragma unroll 8
    for (int k = 0; k < 64; k++) {
        float xv = sX[threadIdx.x * 65 + k];
        #pragma unroll
        for (int j = 0; j < 7; j++) a[j] += xv * sW[k * 8 + j];
    }
    if (n < N_NODES) {
        __half2 h0 = __floats2half2_rn(a[0], a[1]);
        __half2 h1 = __floats2half2_rn(a[2], a[3]);
        __half2 h2 = __floats2half2_rn(a[4], a[5]);
        __half2 h3 = __floats2half2_rn(a[6], 0.f);
        uint4 pk = {*(unsigned*)&h0, *(unsigned*)&h1, *(unsigned*)&h2, *(unsigned*)&h3};
        *(uint4*)&g_h3h[n * 8] = pk;
    }
}

// -------- aggregation 7ch (fp16 in) + bias + log_softmax, thread per node --------

__global__ __launch_bounds__(256) void k_agg7(const float* __restrict__ b3,
                                              float* __restrict__ out) {
    int n = blockIdx.x * blockDim.x + threadIdx.x;
    if (n >= N_NODES) return;
    int cnt = min(g_cnt[n], BKT);
    const unsigned short* __restrict__ row = g_bucket + n * BKT;
    const uint4* __restrict__ p = (const uint4*)g_h3h;
    float a[7] = {};
    int e = 0;
    for (; e + 2 <= cnt; e += 2) {
        int s0 = row[e], s1 = row[e + 1];
        uint4 q0 = p[s0];
        uint4 q1 = p[s1];
        float2 f0 = __half22float2(*(__half2*)&q0.x);
        float2 f1 = __half22float2(*(__half2*)&q0.y);
        float2 f2 = __half22float2(*(__half2*)&q0.z);
        float2 f3 = __half22float2(*(__half2*)&q0.w);
        float2 g0 = __half22float2(*(__half2*)&q1.x);
        float2 g1 = __half22float2(*(__half2*)&q1.y);
        float2 g2 = __half22float2(*(__half2*)&q1.z);
        float2 g3 = __half22float2(*(__half2*)&q1.w);
        a[0] += f0.x + g0.x; a[1] += f0.y + g0.y; a[2] += f1.x + g1.x;
        a[3] += f1.y + g1.y; a[4] += f2.x + g2.x; a[5] += f2.y + g2.y;
        a[6] += f3.x + g3.x;
    }
    for (; e < cnt; e++) {
        uint4 q = p[row[e]];
        float2 f0 = __half22float2(*(__half2*)&q.x);
        float2 f1 = __half22float2(*(__half2*)&q.y);
        float2 f2 = __half22float2(*(__half2*)&q.z);
        float2 f3 = __half22float2(*(__half2*)&q.w);
        a[0] += f0.x; a[1] += f0.y; a[2] += f1.x; a[3] += f1.y;
        a[4] += f2.x; a[5] += f2.y; a[6] += f3.x;
    }
    #pragma unroll
    for (int j = 0; j < 7; j++) a[j] += b3[j];
    float m = a[0];
    #pragma unroll
    for (int j = 1; j < 7; j++) m = fmaxf(m, a[j]);
    float se = 0.f;
    #pragma unroll
    for (int j = 0; j < 7; j++) se += __expf(a[j] - m);
    float ls = __logf(se);
    #pragma unroll
    for (int j = 0; j < 7; j++) out[n * 7 + j] = a[j] - m - ls;
}

// ---------------- launch (fork/join: scatter overlaps prep+gemm1) ----------------

static cudaStream_t g_s2 = nullptr;
static cudaEvent_t g_evF = nullptr, g_evJ = nullptr;

extern "C" void kernel_launch(void* const* d_in, const int* in_sizes, int n_in,
                              void* d_out, int out_size) {
    const float* x = (const float*)d_in[0];
    const int* ei = (const int*)d_in[1];
    const float* W1 = (const float*)d_in[2];
    const float* b1 = (const float*)d_in[3];
    const float* W2 = (const float*)d_in[4];
    const float* b2 = (const float*)d_in[5];
    const float* W3 = (const float*)d_in[6];
    const float* b3 = (const float*)d_in[7];
    float* out = (float*)d_out;

    if (!g_s2) {
        cudaStreamCreateWithFlags(&g_s2, cudaStreamNonBlocking);
        cudaEventCreateWithFlags(&g_evF, cudaEventDisableTiming);
        cudaEventCreateWithFlags(&g_evJ, cudaEventDisableTiming);
    }

    void *pA, *pB, *pw1, *pw2, *pcnt;
    cudaGetSymbolAddress(&pA, g_hA);
    cudaGetSymbolAddress(&pB, g_bufB);
    cudaGetSymbolAddress(&pw1, g_wt1);
    cudaGetSymbolAddress(&pw2, g_wt2);
    cudaGetSymbolAddress(&pcnt, g_cnt);

    // fork: bucket build on side stream (no hist, no scan)
    cudaEventRecord(g_evF, 0);
    cudaStreamWaitEvent(g_s2, g_evF, 0);
    cudaMemsetAsync(pcnt, 0, N_NODES * sizeof(int), g_s2);
    k_scatter<<<(N_EDGES / 8 + 255) / 256, 256, 0, g_s2>>>(ei);
    cudaEventRecord(g_evJ, g_s2);

    // main stream: weight prep + layer-1 GEMM (independent of buckets)
    k_prep_w<<<16, 256>>>(W1, W2, W3);
    k_gemm64h<<<(N_NODES + 63) / 64, 256>>>(x, (const float*)pw1, (__half*)pA);

    // join
    cudaStreamWaitEvent(0, g_evJ, 0);

    // layer 2
    k_agg64h<true><<<(N_NODES * 32 + 255) / 256, 256>>>((const __half2*)pA, b1, (float*)pB);
    k_gemm64h<<<(N_NODES + 63) / 64, 256>>>((const float*)pB, (const float*)pw2, (__half*)pA);
    // layer 3
    k_agg64h<true><<<(N_NODES * 32 + 255) / 256, 256>>>((const __half2*)pA, b2, (float*)pB);
    k_gemm7<<<(N_NODES + 127) / 128, 128>>>((const float*)pB);
    k_agg7<<<(N_NODES + 255) / 256, 256>>>(b3, out);
}

// round 9
// speedup vs baseline: 1.3116x; 1.0802x over previous
#include <cuda_runtime.h>
#include <cuda_fp16.h>

#define N_NODES 50000
#define N_EDGES 1600000
#define BKT 128  // fixed bucket capacity per dst (deg ~ Poisson(32); P(>128) ~ 1e-40)

// ---- scratch (static __device__, no allocs) ----
__device__ int g_cnt[N_NODES];
__device__ __align__(16) unsigned short g_bucket[N_NODES * BKT];
__device__ __half g_hA[N_NODES * 64];    // pre-agg features, fp16
__device__ float g_bufB[N_NODES * 64];   // post-agg features, fp32
__device__ __half g_h3h[N_NODES * 8];    // layer-3 pre-agg, fp16 (7 used + pad)
__device__ float g_wt1[64 * 64];
__device__ float g_wt2[64 * 64];
__device__ float g_wt3[64 * 8];          // [k*8+j]

// ------ zero counters + weight transposes, one index-dispatched kernel ------

__global__ void k_zero_prep(const float* __restrict__ W1, const float* __restrict__ W2,
                            const float* __restrict__ W3) {
    int i = blockIdx.x * blockDim.x + threadIdx.x;
    if (i < N_NODES) { g_cnt[i] = 0; return; }
    int t = i - N_NODES;
    if (t < 4096) { int j = t >> 6, k = t & 63; g_wt1[k * 64 + j] = W1[t]; return; }
    t -= 4096;
    if (t < 4096) { int j = t >> 6, k = t & 63; g_wt2[k * 64 + j] = W2[t]; return; }
    t -= 4096;
    if (t < 512) { int k = t >> 3, j = t & 7; g_wt3[t] = (j < 7) ? W3[j * 64 + k] : 0.f; }
}

// ------ direct bucket scatter: no hist, no scan; 8 edges/thread ------

__global__ void k_scatter(const int* __restrict__ ei) {
    int i = (blockIdx.x * blockDim.x + threadIdx.x) * 8;
    if (i < N_EDGES) {
        int4 sA = *(const int4*)&ei[i];
        int4 sB = *(const int4*)&ei[i + 4];
        int4 dA = *(const int4*)&ei[N_EDGES + i];
        int4 dB = *(const int4*)&ei[N_EDGES + i + 4];
        int p0 = ((unsigned)dA.x < N_NODES) ? atomicAdd(&g_cnt[dA.x], 1) : -1;
        int p1 = ((unsigned)dA.y < N_NODES) ? atomicAdd(&g_cnt[dA.y], 1) : -1;
        int p2 = ((unsigned)dA.z < N_NODES) ? atomicAdd(&g_cnt[dA.z], 1) : -1;
        int p3 = ((unsigned)dA.w < N_NODES) ? atomicAdd(&g_cnt[dA.w], 1) : -1;
        int p4 = ((unsigned)dB.x < N_NODES) ? atomicAdd(&g_cnt[dB.x], 1) : -1;
        int p5 = ((unsigned)dB.y < N_NODES) ? atomicAdd(&g_cnt[dB.y], 1) : -1;
        int p6 = ((unsigned)dB.z < N_NODES) ? atomicAdd(&g_cnt[dB.z], 1) : -1;
        int p7 = ((unsigned)dB.w < N_NODES) ? atomicAdd(&g_cnt[dB.w], 1) : -1;
        if ((unsigned)p0 < BKT) g_bucket[dA.x * BKT + p0] = (unsigned short)sA.x;
        if ((unsigned)p1 < BKT) g_bucket[dA.y * BKT + p1] = (unsigned short)sA.y;
        if ((unsigned)p2 < BKT) g_bucket[dA.z * BKT + p2] = (unsigned short)sA.z;
        if ((unsigned)p3 < BKT) g_bucket[dA.w * BKT + p3] = (unsigned short)sA.w;
        if ((unsigned)p4 < BKT) g_bucket[dB.x * BKT + p4] = (unsigned short)sB.x;
        if ((unsigned)p5 < BKT) g_bucket[dB.y * BKT + p5] = (unsigned short)sB.y;
        if ((unsigned)p6 < BKT) g_bucket[dB.z * BKT + p6] = (unsigned short)sB.z;
        if ((unsigned)p7 < BKT) g_bucket[dB.w * BKT + p7] = (unsigned short)sB.w;
    }
}

// ---- packed f32x2 helpers (Blackwell FFMA2) ----

__device__ __forceinline__ unsigned long long pack2(float lo, float hi) {
    unsigned long long p;
    asm("mov.b64 %0, {%1, %2};" : "=l"(p) : "f"(lo), "f"(hi));
    return p;
}
__device__ __forceinline__ void unpack2(unsigned long long p, float& lo, float& hi) {
    asm("mov.b64 {%0, %1}, %2;" : "=f"(lo), "=f"(hi) : "l"(p));
}
__device__ __forceinline__ void ffma2(unsigned long long& d, unsigned long long a,
                                      unsigned long long b) {
    asm("fma.rn.f32x2 %0, %1, %2, %0;" : "+l"(d) : "l"(a), "l"(b));
}

// ------- GEMM 64x64 fp32-in -> fp16 out, f32x2 packed FMA -------

__global__ __launch_bounds__(256) void k_gemm64h(const float* __restrict__ in,
                                                 const float* __restrict__ wt,
                                                 __half* __restrict__ out) {
    __shared__ __align__(16) float sW[64 * 64];
    __shared__ float sX[64 * 65];
    int n0 = blockIdx.x * 64;
    for (int i = threadIdx.x; i < 4096; i += 256) sW[i] = wt[i];
    for (int i = threadIdx.x; i < 4096; i += 256) {
        int n = i >> 6, k = i & 63;
        sX[n * 65 + k] = (n0 + n < N_NODES) ? in[(n0 + n) * 64 + k] : 0.f;
    }
    __syncthreads();
    int tx = threadIdx.x & 15, ty = threadIdx.x >> 4;
    unsigned long long accP[4][2] = {};
    #pragma unroll 8
    for (int k = 0; k < 64; k++) {
        double2 wd = *(const double2*)&sW[k * 64 + tx * 4];
        unsigned long long w01 = __double_as_longlong(wd.x);
        unsigned long long w23 = __double_as_longlong(wd.y);
        #pragma unroll
        for (int i = 0; i < 4; i++) {
            float xv = sX[(ty * 4 + i) * 65 + k];
            unsigned long long xp = pack2(xv, xv);
            ffma2(accP[i][0], xp, w01);
            ffma2(accP[i][1], xp, w23);
        }
    }
    #pragma unroll
    for (int i = 0; i < 4; i++) {
        int n = n0 + ty * 4 + i;
        if (n < N_NODES) {
            float a0, a1, a2, a3;
            unpack2(accP[i][0], a0, a1);
            unpack2(accP[i][1], a2, a3);
            __half2 h0 = __floats2half2_rn(a0, a1);
            __half2 h1 = __floats2half2_rn(a2, a3);
            uint2 pk = {*(unsigned*)&h0, *(unsigned*)&h1};
            *(uint2*)&out[n * 64 + tx * 4] = pk;
        }
    }
}

// ---- aggregation 64ch, wide geometry: warp/node, 16 lanes x 4ch, 2 edge slots ----
// PROJ=false: +bias,relu -> fp32 out.  PROJ=true: +bias,relu -> @W3 -> fp16 g_h3h.

template <bool PROJ>
__global__ __launch_bounds__(256) void k_agg64v(const uint2* __restrict__ f2,
                                                const float* __restrict__ bias,
                                                float* __restrict__ out) {
    __shared__ float sW3T[512];  // transposed W3: [j*64 + k]
    if (PROJ) {
        for (int i = threadIdx.x; i < 512; i += 256) {
            int j = i >> 6, k = i & 63;
            sW3T[i] = g_wt3[k * 8 + j];
        }
        __syncthreads();
    }
    int n = (blockIdx.x * blockDim.x + threadIdx.x) >> 5;
    int lane = threadIdx.x & 31;
    if (n >= N_NODES) return;
    int cl = lane & 15;            // channel group: 4 ch = [cl*4, cl*4+4)
    int eslot = lane >> 4;         // which edge of each pair
    int sh = eslot << 4;
    int cnt = min(g_cnt[n], BKT);
    const unsigned short* __restrict__ row = g_bucket + n * BKT;
    const uint4* __restrict__ idx4 = (const uint4*)row;
    float a0 = 0.f, a1 = 0.f, a2 = 0.f, a3 = 0.f;
    int e = 0;
    for (; e + 8 <= cnt; e += 8) {
        uint4 q = idx4[e >> 3];
        int s0 = (q.x >> sh) & 0xFFFF;
        int s1 = (q.y >> sh) & 0xFFFF;
        int s2 = (q.z >> sh) & 0xFFFF;
        int s3 = (q.w >> sh) & 0xFFFF;
        uint2 u0 = f2[s0 * 16 + cl];
        uint2 u1 = f2[s1 * 16 + cl];
        uint2 u2 = f2[s2 * 16 + cl];
        uint2 u3 = f2[s3 * 16 + cl];
        float2 p;
        p = __half22float2(*(__half2*)&u0.x); a0 += p.x; a1 += p.y;
        p = __half22float2(*(__half2*)&u0.y); a2 += p.x; a3 += p.y;
        p = __half22float2(*(__half2*)&u1.x); a0 += p.x; a1 += p.y;
        p = __half22float2(*(__half2*)&u1.y); a2 += p.x; a3 += p.y;
        p = __half22float2(*(__half2*)&u2.x); a0 += p.x; a1 += p.y;
        p = __half22float2(*(__half2*)&u2.y); a2 += p.x; a3 += p.y;
        p = __half22float2(*(__half2*)&u3.x); a0 += p.x; a1 += p.y;
        p = __half22float2(*(__half2*)&u3.y); a2 += p.x; a3 += p.y;
    }
    for (; e < cnt; e += 2) {      // tail: warp-uniform bound, per-slot guard
        if (e + eslot < cnt) {
            int s = row[e + eslot];
            uint2 u = f2[s * 16 + cl];
            float2 p;
            p = __half22float2(*(__half2*)&u.x); a0 += p.x; a1 += p.y;
            p = __half22float2(*(__half2*)&u.y); a2 += p.x; a3 += p.y;
        }
    }
    // combine the two edge-slot halves
    a0 += __shfl_xor_sync(~0u, a0, 16);
    a1 += __shfl_xor_sync(~0u, a1, 16);
    a2 += __shfl_xor_sync(~0u, a2, 16);
    a3 += __shfl_xor_sync(~0u, a3, 16);
    float4 b = ((const float4*)bias)[cl];
    a0 = fmaxf(a0 + b.x, 0.f);
    a1 = fmaxf(a1 + b.y, 0.f);
    a2 = fmaxf(a2 + b.z, 0.f);
    a3 = fmaxf(a3 + b.w, 0.f);
    if (!PROJ) {
        if (eslot == 0)
            ((float4*)out)[n * 16 + cl] = make_float4(a0, a1, a2, a3);
    } else {
        // project 64 -> 7 (no bias here; b3 added post-aggregation in k_agg7)
        float pj[7];
        int k0 = cl * 4;
        #pragma unroll
        for (int j = 0; j < 7; j++) {
            const float* wj = &sW3T[j * 64 + k0];
            pj[j] = a0 * wj[0] + a1 * wj[1] + a2 * wj[2] + a3 * wj[3];
        }
        #pragma unroll
        for (int o = 8; o; o >>= 1)
            #pragma unroll
            for (int j = 0; j < 7; j++)
                pj[j] += __shfl_xor_sync(~0u, pj[j], o, 16);
        if (lane == 0) {
            __half2 h0 = __floats2half2_rn(pj[0], pj[1]);
            __half2 h1 = __floats2half2_rn(pj[2], pj[3]);
            __half2 h2v = __floats2half2_rn(pj[4], pj[5]);
            __half2 h3v = __floats2half2_rn(pj[6], 0.f);
            uint4 pk = {*(unsigned*)&h0, *(unsigned*)&h1,
                        *(unsigned*)&h2v, *(unsigned*)&h3v};
            *(uint4*)&g_h3h[n * 8] = pk;
        }
    }
}

// -------- aggregation 7ch (fp16 in) + bias + log_softmax, thread per node --------

__global__ __launch_bounds__(256) void k_agg7(const float* __restrict__ b3,
                                              float* __restrict__ out) {
    int n = blockIdx.x * blockDim.x + threadIdx.x;
    if (n >= N_NODES) return;
    int cnt = min(g_cnt[n], BKT);
    const unsigned short* __restrict__ row = g_bucket + n * BKT;
    const uint4* __restrict__ p = (const uint4*)g_h3h;
    float a[7] = {};
    int e = 0;
    for (; e + 2 <= cnt; e += 2) {
        int s0 = row[e], s1 = row[e + 1];
        uint4 q0 = p[s0];
        uint4 q1 = p[s1];
        float2 f0 = __half22float2(*(__half2*)&q0.x);
        float2 f1 = __half22float2(*(__half2*)&q0.y);
        float2 f2v = __half22float2(*(__half2*)&q0.z);
        float2 f3 = __half22float2(*(__half2*)&q0.w);
        float2 g0 = __half22float2(*(__half2*)&q1.x);
        float2 g1 = __half22float2(*(__half2*)&q1.y);
        float2 g2 = __half22float2(*(__half2*)&q1.z);
        float2 g3 = __half22float2(*(__half2*)&q1.w);
        a[0] += f0.x + g0.x; a[1] += f0.y + g0.y; a[2] += f1.x + g1.x;
        a[3] += f1.y + g1.y; a[4] += f2v.x + g2.x; a[5] += f2v.y + g2.y;
        a[6] += f3.x + g3.x;
    }
    for (; e < cnt; e++) {
        uint4 q = p[row[e]];
        float2 f0 = __half22float2(*(__half2*)&q.x);
        float2 f1 = __half22float2(*(__half2*)&q.y);
        float2 f2v = __half22float2(*(__half2*)&q.z);
        float2 f3 = __half22float2(*(__half2*)&q.w);
        a[0] += f0.x; a[1] += f0.y; a[2] += f1.x; a[3] += f1.y;
        a[4] += f2v.x; a[5] += f2v.y; a[6] += f3.x;
    }
    #pragma unroll
    for (int j = 0; j < 7; j++) a[j] += b3[j];
    float m = a[0];
    #pragma unroll
    for (int j = 1; j < 7; j++) m = fmaxf(m, a[j]);
    float se = 0.f;
    #pragma unroll
    for (int j = 0; j < 7; j++) se += __expf(a[j] - m);
    float ls = __logf(se);
    #pragma unroll
    for (int j = 0; j < 7; j++) out[n * 7 + j] = a[j] - m - ls;
}

// ---------------- launch ----------------

static cudaStream_t g_s2 = nullptr;
static cudaEvent_t g_evF = nullptr, g_evJ = nullptr;

extern "C" void kernel_launch(void* const* d_in, const int* in_sizes, int n_in,
                              void* d_out, int out_size) {
    const float* x = (const float*)d_in[0];
    const int* ei = (const int*)d_in[1];
    const float* W1 = (const float*)d_in[2];
    const float* b1 = (const float*)d_in[3];
    const float* W2 = (const float*)d_in[4];
    const float* b2 = (const float*)d_in[5];
    const float* W3 = (const float*)d_in[6];
    const float* b3 = (const float*)d_in[7];
    float* out = (float*)d_out;

    if (!g_s2) {
        cudaStreamCreateWithFlags(&g_s2, cudaStreamNonBlocking);
        cudaEventCreateWithFlags(&g_evF, cudaEventDisableTiming);
        cudaEventCreateWithFlags(&g_evJ, cudaEventDisableTiming);
    }

    void *pA, *pB, *pw1, *pw2;
    cudaGetSymbolAddress(&pA, g_hA);
    cudaGetSymbolAddress(&pB, g_bufB);
    cudaGetSymbolAddress(&pw1, g_wt1);
    cudaGetSymbolAddress(&pw2, g_wt2);

    // zero counters + weight transposes (one kernel, main stream)
    k_zero_prep<<<(N_NODES + 8704 + 255) / 256, 256>>>(W1, W2, W3);

    // fork: bucket scatter on side stream (needs zeroed counters)
    cudaEventRecord(g_evF, 0);
    cudaStreamWaitEvent(g_s2, g_evF, 0);
    k_scatter<<<(N_EDGES / 8 + 255) / 256, 256, 0, g_s2>>>(ei);
    cudaEventRecord(g_evJ, g_s2);

    // main stream: layer-1 GEMM (independent of buckets)
    k_gemm64h<<<(N_NODES + 63) / 64, 256>>>(x, (const float*)pw1, (__half*)pA);

    // join
    cudaStreamWaitEvent(0, g_evJ, 0);

    // layer 2
    k_agg64v<false><<<(N_NODES * 32 + 255) / 256, 256>>>((const uint2*)pA, b1, (float*)pB);
    k_gemm64h<<<(N_NODES + 63) / 64, 256>>>((const float*)pB, (const float*)pw2, (__half*)pA);
    // layer 3: agg + fused projection, then final agg + log_softmax
    k_agg64v<true><<<(N_NODES * 32 + 255) / 256, 256>>>((const uint2*)pA, b2, nullptr);
    k_agg7<<<(N_NODES + 255) / 256, 256>>>(b3, out);
}